// round 1
// baseline (speedup 1.0000x reference)
#include <cuda_runtime.h>
#include <cuda_bf16.h>
#include <math.h>

#define NB 256
#define BATCHN 128
#define NSTEPS 100
#define MAXEV 5
#define HID 64
#define NTH 512

__device__ __forceinline__ float silu_f(float x) {
    return x / (1.0f + expf(-x));
}

__global__ __launch_bounds__(NTH, 1)
void hybrid_rollout(const float* __restrict__ g_state,
                    const float* __restrict__ g_radii,
                    const float* __restrict__ g_W1,
                    const float* __restrict__ g_b1,
                    const float* __restrict__ g_W2,
                    const float* __restrict__ g_b2,
                    const float* __restrict__ g_W3,
                    const float* __restrict__ g_b3,
                    float* __restrict__ g_out)
{
    __shared__ float4 own[NB];               // this block's batch element
    __shared__ float4 bb0[NB];               // private copy of batch element 0
    __shared__ float w2t[HID*HID];           // W2 transposed: w2t[k*HID+o] = W2[o,k]
    __shared__ float w1s[2*HID];
    __shared__ float b1s[HID], b2s[HID], w3s[HID];
    __shared__ float h1buf[2*HID], h2buf[2*HID];
    __shared__ unsigned long long redB[NTH/32], redW[NTH/32];
    __shared__ unsigned long long sKB, sKW;
    __shared__ int sIJ[2];
    __shared__ float sb3, srr;

    const int tid  = threadIdx.x;
    const int bidx = blockIdx.x;
    const int i0   = tid & (NB-1);
    const int half = tid >> 8;
    const int lane = tid & 31;
    const int warp = tid >> 5;

    // ---- load state, weights; emit initial trajectory slab ----
    if (tid < NB) {
        float4 v = reinterpret_cast<const float4*>(g_state)[bidx*NB + tid];
        own[tid] = v;
        bb0[tid] = reinterpret_cast<const float4*>(g_state)[tid];
        reinterpret_cast<float4*>(g_out)[bidx*NB + tid] = v;
    }
    for (int k = tid; k < HID*HID; k += NTH) {
        int o = k >> 6, c = k & 63;
        w2t[c*HID + o] = g_W2[k];
    }
    if (tid < 2*HID) w1s[tid] = g_W1[tid];
    if (tid < HID) { b1s[tid] = g_b1[tid]; b2s[tid] = g_b2[tid]; w3s[tid] = g_W3[tid]; }
    if (tid == 0) { sb3 = g_b3[0]; srr = g_radii[0]; }
    __syncthreads();

    const float rr    = srr;
    const float two_r = rr + rr;
    const float cut   = two_r + 0.051f;      // generous: any included pair with gap>0.05 -> done anyway
    const float c2    = cut * cut;
    const float b3v   = sb3;
    const int   basei = i0*(2*NB - 1 - i0) / 2;   // triu linear base index for row i0
    const int   dmax  = NB - i0;

    for (int s = 0; s < NSTEPS; ++s) {
        const float t_s = (float)s * 0.05f;
        const float t_e = t_s + 0.05f;
        float t_c = t_s;

        for (int ev = 0; ev < MAXEV; ++ev) {
            // ================= detection (batch-0 copy) =================
            const float4 me = bb0[i0];
            unsigned long long bk = ~0ull;
            for (int d = 1 + half; d < dmax; d += 2) {
                float4 oj = bb0[i0 + d];
                float dx = oj.x - me.x, dy = oj.y - me.y;
                float d2 = dx*dx + dy*dy;
                float dvx = oj.z - me.z, dvy = oj.w - me.w;
                float dd = dvx*dx + dvy*dy;           // sign(app)
                if (dd < 0.0f && d2 <= c2) {
                    unsigned long long key =
                        ((unsigned long long)__float_as_uint(d2) << 32) |
                        (unsigned)(basei + d - 1);
                    if (key < bk) bk = key;
                }
            }
            unsigned long long wk = ~0ull;
            if (half == 0) {
                float gs[4]; bool vs[4];
                gs[0] = me.x - rr;          vs[0] = me.z < 0.0f;
                gs[1] = 10.0f - me.x - rr;  vs[1] = me.z > 0.0f;
                gs[2] = me.y - rr;          vs[2] = me.w < 0.0f;
                gs[3] = 10.0f - me.y - rr;  vs[3] = me.w > 0.0f;
                #pragma unroll
                for (int w = 0; w < 4; ++w) {
                    if (vs[w]) {
                        unsigned u = __float_as_uint(gs[w]);
                        u = (u & 0x80000000u) ? ~u : (u | 0x80000000u);  // monotone float->uint
                        unsigned long long key = ((unsigned long long)u << 32) | (unsigned)(i0*4 + w);
                        if (key < wk) wk = key;
                    }
                }
            }
            // block min-reduction of both keys
            #pragma unroll
            for (int off = 16; off > 0; off >>= 1) {
                unsigned long long ob = __shfl_down_sync(0xFFFFFFFFu, bk, off);
                unsigned long long ow = __shfl_down_sync(0xFFFFFFFFu, wk, off);
                if (ob < bk) bk = ob;
                if (ow < wk) wk = ow;
            }
            if (lane == 0) { redB[warp] = bk; redW[warp] = wk; }
            __syncthreads();
            if (warp == 0) {
                bk = (lane < NTH/32) ? redB[lane] : ~0ull;
                wk = (lane < NTH/32) ? redW[lane] : ~0ull;
                #pragma unroll
                for (int off = 8; off > 0; off >>= 1) {
                    unsigned long long ob = __shfl_down_sync(0xFFFFFFFFu, bk, off);
                    unsigned long long ow = __shfl_down_sync(0xFFFFFFFFu, wk, off);
                    if (ob < bk) bk = ob;
                    if (ow < wk) wk = ow;
                }
                if (lane == 0) { sKB = bk; sKW = wk; }
            }
            __syncthreads();
            const unsigned long long kb = sKB, kw = sKW;

            float gapB = 1e30f, gapW = 1e30f;
            if (kb != ~0ull) gapB = sqrtf(__uint_as_float((unsigned)(kb >> 32))) - two_r;
            if (kw != ~0ull) {
                unsigned u = (unsigned)(kw >> 32);
                u = (u & 0x80000000u) ? (u ^ 0x80000000u) : ~u;
                gapW = __uint_as_float(u);
            }
            const bool  is_ball = (gapB <= gapW);   // ties -> ball (lower concat index)
            const float gap     = is_ball ? gapB : gapW;
            if (gap > 0.05f) break;                  // no_event -> done

            // decode winner indices
            int iA, iB = 0, wsel = 0;
            if (is_ball) {
                unsigned k = (unsigned)kb;
                if (half == 0 && k >= (unsigned)basei && (int)(k - (unsigned)basei) < NB - 1 - i0) {
                    sIJ[0] = i0;
                    sIJ[1] = i0 + (int)(k - (unsigned)basei) + 1;
                }
                __syncthreads();
                iA = sIJ[0]; iB = sIJ[1];
            } else {
                unsigned k = (unsigned)kw;
                iA = (int)(k >> 2); wsel = (int)(k & 3);
                __syncthreads();
            }

            // approach speed (from PRE-integration batch-0 state)
            float app;
            if (is_ball) {
                float4 si = bb0[iA], sj = bb0[iB];
                float nx = sj.x - si.x, ny = sj.y - si.y;
                float L = sqrtf(nx*nx + ny*ny);
                float dvx = sj.z - si.z, dvy = sj.w - si.w;
                app = -((dvx*nx)/L + (dvy*ny)/L);
            } else {
                float4 si = bb0[iA];
                app = fabsf(fmaxf(si.z, si.w));
            }
            const float t_ev  = t_c + gap / fmaxf(app, 1e-6f);
            const bool case_a = (gap <= 0.0f);
            const bool case_b = (!case_a) && (app > 1e-6f) && (t_ev < t_e);
            if (!case_a && !case_b) break;           // done (stall / beyond step end)

            __syncthreads();                          // drain all app/state reads
            if (case_b) {
                const float dte = (t_ev > t_c + 1e-10f) ? (t_ev - t_c) : 0.0f;
                if (tid < NB) {
                    own[tid].x += own[tid].z * dte;  own[tid].y += own[tid].w * dte;
                    bb0[tid].x += bb0[tid].z * dte;  bb0[tid].y += bb0[tid].w * dte;
                }
                t_c = t_ev;
                __syncthreads();
            }

            // ================= apply event (to own element AND batch-0 copy) =================
            if (is_ball) {
                if (tid < 2*HID) {                   // threads 0-63: own, 64-127: bb0
                    int sel = tid >> 6, o = tid & (HID-1);
                    const float4* S = sel ? bb0 : own;
                    float4 si = S[iA], sj = S[iB];
                    float dx = sj.x - si.x, dy = sj.y - si.y;
                    float dist = fmaxf(sqrtf(dx*dx + dy*dy), 1e-8f);
                    float nx = dx / dist, ny = dy / dist;
                    float ap = (sj.z - si.z)*nx + (sj.w - si.w)*ny;
                    float pre = dist*w1s[2*o] + ap*w1s[2*o+1] + b1s[o];
                    h1buf[sel*HID + o] = silu_f(pre);
                }
                __syncthreads();
                if (tid < 2*HID) {
                    int sel = tid >> 6, o = tid & (HID-1);
                    float acc = b2s[o];
                    const float* hb = &h1buf[sel*HID];
                    #pragma unroll
                    for (int k2 = 0; k2 < HID; ++k2) acc += w2t[k2*HID + o]*hb[k2];
                    h2buf[sel*HID + o] = w3s[o] * silu_f(acc);
                }
                __syncthreads();
                if (warp == 0 || warp == 2) {        // warp0 -> own, warp2 -> bb0
                    int sel = warp >> 1;
                    float v = h2buf[sel*HID + lane] + h2buf[sel*HID + 32 + lane];
                    #pragma unroll
                    for (int off = 16; off > 0; off >>= 1)
                        v += __shfl_down_sync(0xFFFFFFFFu, v, off);
                    if (lane == 0) {
                        float impv = v + b3v;
                        float4* S = sel ? bb0 : own;
                        float4 si = S[iA], sj = S[iB];
                        float dx = sj.x - si.x, dy = sj.y - si.y;
                        float dist = fmaxf(sqrtf(dx*dx + dy*dy), 1e-8f);
                        float nx = dx/dist, ny = dy/dist;
                        S[iA].z = si.z + impv*nx;  S[iA].w = si.w + impv*ny;
                        S[iB].z = sj.z - impv*nx;  S[iB].w = sj.w - impv*ny;
                    }
                }
            } else {
                if (tid < 2) {                        // thread0 -> own, thread1 -> bb0
                    float4* S = tid ? bb0 : own;
                    float4 si = S[iA];
                    float wnx = 0.0f, wny = 0.0f, wp = 0.0f;
                    if      (wsel == 0) { wnx =  1.0f; }
                    else if (wsel == 1) { wnx = -1.0f; wp = -10.0f; }
                    else if (wsel == 2) { wny =  1.0f; }
                    else                { wny = -1.0f; wp = -10.0f; }
                    float vn  = si.z*wnx + si.w*wny;
                    float nvx = si.z - 2.0f*vn*wnx;
                    float nvy = si.w - 2.0f*vn*wny;
                    float pn  = si.x*wnx + si.y*wny;
                    float pen = fmaxf(wp + rr - pn, 0.0f);
                    S[iA] = make_float4(si.x + pen*wnx, si.y + pen*wny, nvx, nvy);
                }
            }
            __syncthreads();
        }  // events

        // ---- end of step: integrate remaining time, emit trajectory ----
        __syncthreads();
        const float dte2 = (t_e > t_c + 1e-10f) ? (t_e - t_c) : 0.0f;
        if (tid < NB) {
            float4 v = own[tid];
            v.x += v.z * dte2; v.y += v.w * dte2;
            own[tid] = v;
            float4 c = bb0[tid];
            c.x += c.z * dte2; c.y += c.w * dte2;
            bb0[tid] = c;
            reinterpret_cast<float4*>(g_out)[((long)(s+1)*BATCHN + bidx)*NB + tid] = v;
        }
        __syncthreads();
    }
}

extern "C" void kernel_launch(void* const* d_in, const int* in_sizes, int n_in,
                              void* d_out, int out_size) {
    (void)in_sizes; (void)n_in; (void)out_size;
    hybrid_rollout<<<BATCHN, NTH>>>(
        (const float*)d_in[0], (const float*)d_in[1],
        (const float*)d_in[2], (const float*)d_in[3],
        (const float*)d_in[4], (const float*)d_in[5],
        (const float*)d_in[6], (const float*)d_in[7],
        (float*)d_out);
}

// round 2
// speedup vs baseline: 1.3118x; 1.3118x over previous
#include <cuda_runtime.h>
#include <cuda_bf16.h>
#include <math.h>

#define NB 256
#define BATCHN 128
#define NSTEPS 100
#define MAXEV 5
#define HID 64
#define NTH 512
#define CAP 3072
#define MARGIN 0.35f

__device__ __forceinline__ float silu_f(float x) {
    return x / (1.0f + expf(-x));
}

__global__ __launch_bounds__(NTH, 1)
void hybrid_rollout(const float* __restrict__ g_state,
                    const float* __restrict__ g_radii,
                    const float* __restrict__ g_W1,
                    const float* __restrict__ g_b1,
                    const float* __restrict__ g_W2,
                    const float* __restrict__ g_b2,
                    const float* __restrict__ g_W3,
                    const float* __restrict__ g_b3,
                    float* __restrict__ g_out)
{
    __shared__ float4 own[NB];               // this block's batch element
    __shared__ float4 bb0[NB];               // private copy of batch element 0
    __shared__ float w2t[HID*HID];           // W2 transposed: w2t[k*HID+o] = W2[o,k]
    __shared__ float w1s[2*HID];
    __shared__ float b1s[HID], b2s[HID], w3s[HID];
    __shared__ float h1buf[2*HID], h2buf[2*HID];
    __shared__ unsigned long long redB[NTH/32], redW[NTH/32];
    __shared__ unsigned long long sKB, sKW;
    __shared__ int sIJ[2];
    __shared__ float sb3, srr;
    __shared__ int candList[CAP];            // packed (lo<<8)|hi
    __shared__ int nCand;
    __shared__ int sVmax2i;                  // float bits of max speed^2 over bb0 balls
    __shared__ float sMotion;                // pairwise motion bound since last rebuild
    __shared__ int sOverflow;

    const int tid  = threadIdx.x;
    const int bidx = blockIdx.x;
    const int i0   = tid & (NB-1);
    const int half = tid >> 8;
    const int lane = tid & 31;
    const int warp = tid >> 5;

    // ---- load state, weights; emit initial trajectory slab ----
    if (tid < NB) {
        float4 v = reinterpret_cast<const float4*>(g_state)[bidx*NB + tid];
        own[tid] = v;
        bb0[tid] = reinterpret_cast<const float4*>(g_state)[tid];
        reinterpret_cast<float4*>(g_out)[bidx*NB + tid] = v;
    }
    for (int k = tid; k < HID*HID; k += NTH) {
        int o = k >> 6, c = k & 63;
        w2t[c*HID + o] = g_W2[k];
    }
    if (tid < 2*HID) w1s[tid] = g_W1[tid];
    if (tid < HID) { b1s[tid] = g_b1[tid]; b2s[tid] = g_b2[tid]; w3s[tid] = g_W3[tid]; }
    if (tid == 0) {
        sb3 = g_b3[0]; srr = g_radii[0];
        sMotion = 1e30f; sVmax2i = 0; sOverflow = 0; nCand = 0;
    }
    __syncthreads();

    const float rr    = srr;
    const float two_r = rr + rr;
    const float cut   = two_r + 0.051f;      // any included pair with gap>0.05 -> done anyway
    const float c2    = cut * cut;
    const float cute  = cut + MARGIN;        // broad-phase cutoff
    const float c2e   = cute * cute;
    const float b3v   = sb3;

    for (int s = 0; s < NSTEPS; ++s) {
        const float t_s = (float)s * 0.05f;
        const float t_e = t_s + 0.05f;
        float t_c = t_s;

        for (int ev = 0; ev < MAXEV; ++ev) {
            // ================= detection (batch-0 copy) =================
            const bool rebuild = (sOverflow != 0) || (sMotion >= MARGIN);
            const float4 me = bb0[i0];
            unsigned long long bk = ~0ull;

            if (rebuild) {
                if (tid == 0) { nCand = 0; sVmax2i = 0; }
                __syncthreads();
                // recompute vmax^2 over bb0
                float m = (half == 0) ? (me.z*me.z + me.w*me.w) : 0.0f;
                #pragma unroll
                for (int off = 16; off > 0; off >>= 1)
                    m = fmaxf(m, __shfl_down_sync(0xFFFFFFFFu, m, off));
                if (lane == 0) atomicMax(&sVmax2i, __float_as_int(m));
                // balanced rotated pair scan: 64 pairs per thread
                for (int d = 1 + half; d <= 128; d += 2) {
                    if (d == 128 && i0 >= 128) break;
                    int j = (i0 + d) & (NB-1);
                    float4 oj = bb0[j];
                    float dx = oj.x - me.x, dy = oj.y - me.y;
                    float d2 = dx*dx + dy*dy;
                    if (d2 <= c2e) {
                        int lo = (i0 < j) ? i0 : j;
                        int hi = (i0 < j) ? j : i0;
                        int slot = atomicAdd(&nCand, 1);
                        if (slot < CAP) candList[slot] = (lo << 8) | hi;
                        float dvx = oj.z - me.z, dvy = oj.w - me.w;
                        float dd = dvx*dx + dvy*dy;
                        if (dd < 0.0f && d2 <= c2) {
                            unsigned idx = (unsigned)(lo*(2*NB-1-lo)/2 + (hi - lo - 1));
                            unsigned long long key =
                                ((unsigned long long)__float_as_uint(d2) << 32) | idx;
                            if (key < bk) bk = key;
                        }
                    }
                }
            } else {
                const int n = (nCand < CAP) ? nCand : CAP;
                for (int e = tid; e < n; e += NTH) {
                    int p = candList[e];
                    int lo = p >> 8, hi = p & 255;
                    float4 si = bb0[lo], sj = bb0[hi];
                    float dx = sj.x - si.x, dy = sj.y - si.y;
                    float d2 = dx*dx + dy*dy;
                    float dvx = sj.z - si.z, dvy = sj.w - si.w;
                    float dd = dvx*dx + dvy*dy;
                    if (dd < 0.0f && d2 <= c2) {
                        unsigned idx = (unsigned)(lo*(2*NB-1-lo)/2 + (hi - lo - 1));
                        unsigned long long key =
                            ((unsigned long long)__float_as_uint(d2) << 32) | idx;
                        if (key < bk) bk = key;
                    }
                }
            }

            // wall candidates (always fresh; cheap)
            unsigned long long wk = ~0ull;
            if (half == 0) {
                float gs[4]; bool vs[4];
                gs[0] = me.x - rr;          vs[0] = me.z < 0.0f;
                gs[1] = 10.0f - me.x - rr;  vs[1] = me.z > 0.0f;
                gs[2] = me.y - rr;          vs[2] = me.w < 0.0f;
                gs[3] = 10.0f - me.y - rr;  vs[3] = me.w > 0.0f;
                #pragma unroll
                for (int w = 0; w < 4; ++w) {
                    if (vs[w]) {
                        unsigned u = __float_as_uint(gs[w]);
                        u = (u & 0x80000000u) ? ~u : (u | 0x80000000u);  // monotone float->uint
                        unsigned long long key = ((unsigned long long)u << 32) | (unsigned)(i0*4 + w);
                        if (key < wk) wk = key;
                    }
                }
            }

            // block min-reduction of both keys
            #pragma unroll
            for (int off = 16; off > 0; off >>= 1) {
                unsigned long long ob = __shfl_down_sync(0xFFFFFFFFu, bk, off);
                unsigned long long ow = __shfl_down_sync(0xFFFFFFFFu, wk, off);
                if (ob < bk) bk = ob;
                if (ow < wk) wk = ow;
            }
            if (lane == 0) { redB[warp] = bk; redW[warp] = wk; }
            __syncthreads();
            if (warp == 0) {
                bk = (lane < NTH/32) ? redB[lane] : ~0ull;
                wk = (lane < NTH/32) ? redW[lane] : ~0ull;
                #pragma unroll
                for (int off = 8; off > 0; off >>= 1) {
                    unsigned long long ob = __shfl_down_sync(0xFFFFFFFFu, bk, off);
                    unsigned long long ow = __shfl_down_sync(0xFFFFFFFFu, wk, off);
                    if (ob < bk) bk = ob;
                    if (ow < wk) wk = ow;
                }
                if (lane == 0) {
                    sKB = bk; sKW = wk;
                    if (rebuild) {
                        if (nCand > CAP) sOverflow = 1;
                        sMotion = 0.0f;
                    }
                }
            }
            __syncthreads();
            const unsigned long long kb = sKB, kw = sKW;

            float gapB = 1e30f, gapW = 1e30f;
            if (kb != ~0ull) gapB = sqrtf(__uint_as_float((unsigned)(kb >> 32))) - two_r;
            if (kw != ~0ull) {
                unsigned u = (unsigned)(kw >> 32);
                u = (u & 0x80000000u) ? (u ^ 0x80000000u) : ~u;
                gapW = __uint_as_float(u);
            }
            const bool  is_ball = (gapB <= gapW);   // ties -> ball (lower concat index)
            const float gap     = is_ball ? gapB : gapW;
            if (gap > 0.05f) break;                  // no_event -> done

            // decode winner indices
            int iA, iB = 0, wsel = 0;
            if (is_ball) {
                unsigned k = (unsigned)kb;
                unsigned base_t = (unsigned)(i0*(2*NB-1-i0)/2);
                if (half == 0 && k >= base_t && (int)(k - base_t) < NB - 1 - i0) {
                    sIJ[0] = i0;
                    sIJ[1] = i0 + (int)(k - base_t) + 1;
                }
                __syncthreads();
                iA = sIJ[0]; iB = sIJ[1];
            } else {
                unsigned k = (unsigned)kw;
                iA = (int)(k >> 2); wsel = (int)(k & 3);
                __syncthreads();
            }

            // approach speed (from PRE-integration batch-0 state)
            float app;
            if (is_ball) {
                float4 si = bb0[iA], sj = bb0[iB];
                float nx = sj.x - si.x, ny = sj.y - si.y;
                float L = sqrtf(nx*nx + ny*ny);
                float dvx = sj.z - si.z, dvy = sj.w - si.w;
                app = -((dvx*nx)/L + (dvy*ny)/L);
            } else {
                float4 si = bb0[iA];
                app = fabsf(fmaxf(si.z, si.w));
            }
            const float t_ev  = t_c + gap / fmaxf(app, 1e-6f);
            const bool case_a = (gap <= 0.0f);
            const bool case_b = (!case_a) && (app > 1e-6f) && (t_ev < t_e);
            if (!case_a && !case_b) break;           // done (stall / beyond step end)

            __syncthreads();                          // drain all app/state reads
            if (case_b) {
                const float dte = (t_ev > t_c + 1e-10f) ? (t_ev - t_c) : 0.0f;
                if (tid < NB) {
                    own[tid].x += own[tid].z * dte;  own[tid].y += own[tid].w * dte;
                    bb0[tid].x += bb0[tid].z * dte;  bb0[tid].y += bb0[tid].w * dte;
                }
                if (tid == 0)
                    sMotion += 2.0f * sqrtf(__int_as_float(sVmax2i)) * dte;
                t_c = t_ev;
                __syncthreads();
            }

            // ================= apply event (to own element AND batch-0 copy) =================
            if (is_ball) {
                if (tid < 2*HID) {                   // threads 0-63: own, 64-127: bb0
                    int sel = tid >> 6, o = tid & (HID-1);
                    const float4* S = sel ? bb0 : own;
                    float4 si = S[iA], sj = S[iB];
                    float dx = sj.x - si.x, dy = sj.y - si.y;
                    float dist = fmaxf(sqrtf(dx*dx + dy*dy), 1e-8f);
                    float nx = dx / dist, ny = dy / dist;
                    float ap = (sj.z - si.z)*nx + (sj.w - si.w)*ny;
                    float pre = dist*w1s[2*o] + ap*w1s[2*o+1] + b1s[o];
                    h1buf[sel*HID + o] = silu_f(pre);
                }
                __syncthreads();
                if (tid < 2*HID) {
                    int sel = tid >> 6, o = tid & (HID-1);
                    float acc = b2s[o];
                    const float* hb = &h1buf[sel*HID];
                    #pragma unroll
                    for (int k2 = 0; k2 < HID; ++k2) acc += w2t[k2*HID + o]*hb[k2];
                    h2buf[sel*HID + o] = w3s[o] * silu_f(acc);
                }
                __syncthreads();
                if (warp == 0 || warp == 2) {        // warp0 -> own, warp2 -> bb0
                    int sel = warp >> 1;
                    float v = h2buf[sel*HID + lane] + h2buf[sel*HID + 32 + lane];
                    #pragma unroll
                    for (int off = 16; off > 0; off >>= 1)
                        v += __shfl_down_sync(0xFFFFFFFFu, v, off);
                    if (lane == 0) {
                        float impv = v + b3v;
                        float4* S = sel ? bb0 : own;
                        float4 si = S[iA], sj = S[iB];
                        float dx = sj.x - si.x, dy = sj.y - si.y;
                        float dist = fmaxf(sqrtf(dx*dx + dy*dy), 1e-8f);
                        float nx = dx/dist, ny = dy/dist;
                        float niz = si.z + impv*nx, niw = si.w + impv*ny;
                        float njz = sj.z - impv*nx, njw = sj.w - impv*ny;
                        S[iA].z = niz;  S[iA].w = niw;
                        S[iB].z = njz;  S[iB].w = njw;
                        if (sel == 1) {              // track vmax for bb0 geometry
                            float sp = fmaxf(niz*niz + niw*niw, njz*njz + njw*njw);
                            atomicMax(&sVmax2i, __float_as_int(sp));
                        }
                    }
                }
            } else {
                if (tid < 2) {                        // thread0 -> own, thread1 -> bb0
                    float4* S = tid ? bb0 : own;
                    float4 si = S[iA];
                    float wnx = 0.0f, wny = 0.0f, wp = 0.0f;
                    if      (wsel == 0) { wnx =  1.0f; }
                    else if (wsel == 1) { wnx = -1.0f; wp = -10.0f; }
                    else if (wsel == 2) { wny =  1.0f; }
                    else                { wny = -1.0f; wp = -10.0f; }
                    float vn  = si.z*wnx + si.w*wny;
                    float nvx = si.z - 2.0f*vn*wnx;
                    float nvy = si.w - 2.0f*vn*wny;
                    float pn  = si.x*wnx + si.y*wny;
                    float pen = fmaxf(wp + rr - pn, 0.0f);
                    S[iA] = make_float4(si.x + pen*wnx, si.y + pen*wny, nvx, nvy);
                    if (tid == 1) sMotion += pen;     // bb0 moved by pen
                }
            }
            __syncthreads();
        }  // events

        // ---- end of step: integrate remaining time, emit trajectory ----
        __syncthreads();
        const float dte2 = (t_e > t_c + 1e-10f) ? (t_e - t_c) : 0.0f;
        if (tid < NB) {
            float4 v = own[tid];
            v.x += v.z * dte2; v.y += v.w * dte2;
            own[tid] = v;
            float4 c = bb0[tid];
            c.x += c.z * dte2; c.y += c.w * dte2;
            bb0[tid] = c;
            reinterpret_cast<float4*>(g_out)[((long)(s+1)*BATCHN + bidx)*NB + tid] = v;
        }
        if (tid == 0)
            sMotion += 2.0f * sqrtf(__int_as_float(sVmax2i)) * dte2;
        __syncthreads();
    }
}

extern "C" void kernel_launch(void* const* d_in, const int* in_sizes, int n_in,
                              void* d_out, int out_size) {
    (void)in_sizes; (void)n_in; (void)out_size;
    hybrid_rollout<<<BATCHN, NTH>>>(
        (const float*)d_in[0], (const float*)d_in[1],
        (const float*)d_in[2], (const float*)d_in[3],
        (const float*)d_in[4], (const float*)d_in[5],
        (const float*)d_in[6], (const float*)d_in[7],
        (float*)d_out);
}

// round 3
// speedup vs baseline: 1.4647x; 1.1166x over previous
#include <cuda_runtime.h>
#include <cuda_bf16.h>
#include <math.h>

#define NB 256
#define BATCHN 128
#define NSTEPS 100
#define MAXEV 5
#define HID 64
#define NTH 512
#define CAP 3072
#define MARGIN 0.75f

__device__ __forceinline__ float silu_f(float x) {
    return x / (1.0f + expf(-x));
}

__global__ __launch_bounds__(NTH, 1)
void hybrid_rollout(const float* __restrict__ g_state,
                    const float* __restrict__ g_radii,
                    const float* __restrict__ g_W1,
                    const float* __restrict__ g_b1,
                    const float* __restrict__ g_W2,
                    const float* __restrict__ g_b2,
                    const float* __restrict__ g_W3,
                    const float* __restrict__ g_b3,
                    float* __restrict__ g_out)
{
    __shared__ float4 own[NB];               // this block's batch element
    __shared__ float4 bb0[NB];               // private copy of batch element 0
    __shared__ float2 posA[NB];              // position mirror of bb0 (broad phase)
    __shared__ float w2t[HID*HID];           // W2 transposed
    __shared__ float w1s[2*HID];
    __shared__ float b1s[HID], b2s[HID], w3s[HID];
    __shared__ float h1buf[2*HID], h2buf[2*HID];
    __shared__ unsigned long long sKBev[MAXEV], sKWev[MAXEV];
    __shared__ int sIJ[2];                   // ball: iA,iB   wall: iA,wsel
    __shared__ int sFlags;                   // 1=case_a 2=case_b 0=done
    __shared__ float sDte, sTev;
    __shared__ float4 snap[4];               // integrated: ownA, ownB, bb0A, bb0B
    __shared__ float sb3, srr;
    __shared__ int candList[CAP];            // packed (lo<<8)|hi
    __shared__ int nCand;
    __shared__ int sVmax2i;                  // float bits of max speed^2 over bb0
    __shared__ float sMotion;
    __shared__ int sOverflow;

    const int tid  = threadIdx.x;
    const int bidx = blockIdx.x;
    const int i0   = tid & (NB-1);
    const int half = tid >> 8;
    const int lane = tid & 31;
    const int warp = tid >> 5;

    // ---- setup ----
    if (tid < NB) {
        float4 v = reinterpret_cast<const float4*>(g_state)[bidx*NB + tid];
        own[tid] = v;
        float4 c = reinterpret_cast<const float4*>(g_state)[tid];
        bb0[tid] = c;
        posA[tid] = make_float2(c.x, c.y);
        reinterpret_cast<float4*>(g_out)[bidx*NB + tid] = v;
    }
    for (int k = tid; k < HID*HID; k += NTH) {
        int o = k >> 6, c = k & 63;
        w2t[c*HID + o] = g_W2[k];
    }
    if (tid < 2*HID) w1s[tid] = g_W1[tid];
    if (tid < HID) { b1s[tid] = g_b1[tid]; b2s[tid] = g_b2[tid]; w3s[tid] = g_W3[tid]; }
    if (tid < MAXEV) { sKBev[tid] = ~0ull; sKWev[tid] = ~0ull; }
    if (tid == 0) {
        sb3 = g_b3[0]; srr = g_radii[0];
        sMotion = 1e30f; sVmax2i = 0; sOverflow = 0; nCand = 0;
    }
    __syncthreads();

    const float rr    = srr;
    const float two_r = rr + rr;
    const float cut   = two_r + 0.051f;      // exact narrow cutoff (gap>0.05 -> done anyway)
    const float c2    = cut * cut;
    const float cute  = cut + MARGIN;        // broad-phase cutoff
    const float c2e   = cute * cute;
    const float b3v   = sb3;

    for (int s = 0; s < NSTEPS; ++s) {
        const float t_s = (float)s * 0.05f;
        const float t_e = t_s + 0.05f;
        float t_c = t_s;

        for (int ev = 0; ev < MAXEV; ++ev) {
            // ================= P0: detection =================
            const bool rebuild = (sOverflow != 0) || (sMotion >= MARGIN);
            const float4 me = bb0[i0];
            unsigned long long bk = ~0ull;

            if (rebuild) {
                if (tid == 0) { nCand = 0; sVmax2i = 0; }
                __syncthreads();
                // vmax^2 over bb0 velocities (all threads contribute; duplicates ok)
                float m = me.z*me.z + me.w*me.w;
                #pragma unroll
                for (int off = 16; off > 0; off >>= 1)
                    m = fmaxf(m, __shfl_down_sync(0xFFFFFFFFu, m, off));
                if (lane == 0) atomicMax(&sVmax2i, __float_as_int(m));
                // balanced rotated pair scan: 64 pairs/thread, pos-only broad phase
                for (int d = 1 + half; d <= 128; d += 2) {
                    if (d == 128 && i0 >= 128) break;
                    int j = (i0 + d) & (NB-1);
                    float2 pj = posA[j];
                    float dx = pj.x - me.x, dy = pj.y - me.y;
                    float d2 = dx*dx + dy*dy;
                    if (d2 <= c2e) {
                        int lo = (i0 < j) ? i0 : j;
                        int hi = (i0 < j) ? j : i0;
                        int slot = atomicAdd(&nCand, 1);
                        if (slot < CAP) candList[slot] = (lo << 8) | hi;
                        float4 oj = bb0[j];
                        float dvx = oj.z - me.z, dvy = oj.w - me.w;
                        if (dvx*dx + dvy*dy < 0.0f && d2 <= c2) {
                            unsigned idx = (unsigned)(lo*(2*NB-1-lo)/2 + (hi - lo - 1));
                            unsigned long long key =
                                ((unsigned long long)__float_as_uint(d2) << 32) | idx;
                            if (key < bk) bk = key;
                        }
                    }
                }
            } else {
                const int n = (nCand < CAP) ? nCand : CAP;
                for (int e = tid; e < n; e += NTH) {
                    int p = candList[e];
                    int lo = p >> 8, hi = p & 255;
                    float4 si = bb0[lo], sj = bb0[hi];
                    float dx = sj.x - si.x, dy = sj.y - si.y;
                    float d2 = dx*dx + dy*dy;
                    float dvx = sj.z - si.z, dvy = sj.w - si.w;
                    if (dvx*dx + dvy*dy < 0.0f && d2 <= c2) {
                        unsigned idx = (unsigned)(lo*(2*NB-1-lo)/2 + (hi - lo - 1));
                        unsigned long long key =
                            ((unsigned long long)__float_as_uint(d2) << 32) | idx;
                        if (key < bk) bk = key;
                    }
                }
            }

            // wall candidates
            unsigned long long wk = ~0ull;
            if (half == 0) {
                float gs[4]; bool vs[4];
                gs[0] = me.x - rr;          vs[0] = me.z < 0.0f;
                gs[1] = 10.0f - me.x - rr;  vs[1] = me.z > 0.0f;
                gs[2] = me.y - rr;          vs[2] = me.w < 0.0f;
                gs[3] = 10.0f - me.y - rr;  vs[3] = me.w > 0.0f;
                #pragma unroll
                for (int w = 0; w < 4; ++w) {
                    if (vs[w]) {
                        unsigned u = __float_as_uint(gs[w]);
                        u = (u & 0x80000000u) ? ~u : (u | 0x80000000u);
                        unsigned long long key = ((unsigned long long)u << 32) | (unsigned)(i0*4 + w);
                        if (key < wk) wk = key;
                    }
                }
            }

            // warp tree + lane0 atomicMin into pre-reset per-event slots
            #pragma unroll
            for (int off = 16; off > 0; off >>= 1) {
                unsigned long long ob = __shfl_down_sync(0xFFFFFFFFu, bk, off);
                unsigned long long ow = __shfl_down_sync(0xFFFFFFFFu, wk, off);
                if (ob < bk) bk = ob;
                if (ow < wk) wk = ow;
            }
            if (lane == 0) {
                atomicMin(&sKBev[ev], bk);
                atomicMin(&sKWev[ev], wk);
            }
            __syncthreads();                              // ---- BAR A ----

            const unsigned long long kb = sKBev[ev], kw = sKWev[ev];
            if (rebuild && tid == 0) {
                if (nCand > CAP) sOverflow = 1;
                sMotion = 0.0f;
            }

            float gapB = 1e30f, gapW = 1e30f;
            if (kb != ~0ull) gapB = sqrtf(__uint_as_float((unsigned)(kb >> 32))) - two_r;
            if (kw != ~0ull) {
                unsigned u = (unsigned)(kw >> 32);
                u = (u & 0x80000000u) ? (u ^ 0x80000000u) : ~u;
                gapW = __uint_as_float(u);
            }
            const bool  is_ball = (gapB <= gapW);
            const float gap     = is_ball ? gapB : gapW;
            if (gap > 0.05f) break;                        // no_event -> done

            // ================= P1: owner computes flags + snapshots =================
            if (is_ball) {
                unsigned k = (unsigned)kb;
                unsigned base_t = (unsigned)(i0*(2*NB-1-i0)/2);
                if (half == 0 && k >= base_t && (k - base_t) < (unsigned)(NB - 1 - i0)) {
                    int iA = i0, iB = i0 + (int)(k - base_t) + 1;
                    float4 pi = bb0[iA], pj = bb0[iB];
                    float nx = pj.x - pi.x, ny = pj.y - pi.y;
                    float L = sqrtf(nx*nx + ny*ny);
                    float app = -(((pj.z - pi.z)*nx)/L + ((pj.w - pi.w)*ny)/L);
                    float t_ev = t_c + gap / fmaxf(app, 1e-6f);
                    bool ca = (gap <= 0.0f);
                    bool cb = !ca && (app > 1e-6f) && (t_ev < t_e);
                    float dte = cb ? ((t_ev > t_c + 1e-10f) ? (t_ev - t_c) : 0.0f) : 0.0f;
                    sFlags = ca ? 1 : (cb ? 2 : 0);
                    sDte = dte; sTev = t_ev; sIJ[0] = iA; sIJ[1] = iB;
                    float4 oi = own[iA], oj = own[iB];
                    snap[0] = make_float4(fmaf(oi.z,dte,oi.x), fmaf(oi.w,dte,oi.y), oi.z, oi.w);
                    snap[1] = make_float4(fmaf(oj.z,dte,oj.x), fmaf(oj.w,dte,oj.y), oj.z, oj.w);
                    snap[2] = make_float4(fmaf(pi.z,dte,pi.x), fmaf(pi.w,dte,pi.y), pi.z, pi.w);
                    snap[3] = make_float4(fmaf(pj.z,dte,pj.x), fmaf(pj.w,dte,pj.y), pj.z, pj.w);
                }
            } else {
                unsigned k = (unsigned)kw;
                if (half == 0 && i0 == (int)(k >> 2)) {
                    int iA = i0;
                    float4 pi = bb0[iA];
                    float app = fabsf(fmaxf(pi.z, pi.w));
                    float t_ev = t_c + gap / fmaxf(app, 1e-6f);
                    bool ca = (gap <= 0.0f);
                    bool cb = !ca && (app > 1e-6f) && (t_ev < t_e);
                    float dte = cb ? ((t_ev > t_c + 1e-10f) ? (t_ev - t_c) : 0.0f) : 0.0f;
                    sFlags = ca ? 1 : (cb ? 2 : 0);
                    sDte = dte; sTev = t_ev; sIJ[0] = iA; sIJ[1] = (int)(k & 3);
                    float4 oi = own[iA];
                    snap[0] = make_float4(fmaf(oi.z,dte,oi.x), fmaf(oi.w,dte,oi.y), oi.z, oi.w);
                    snap[2] = make_float4(fmaf(pi.z,dte,pi.x), fmaf(pi.w,dte,pi.y), pi.z, pi.w);
                }
            }
            __syncthreads();                              // ---- BAR B ----

            const int flags = sFlags;
            if (flags == 0) break;                         // done
            const float dte = sDte;
            if (flags & 2) t_c = sTev;
            const int iA = sIJ[0];

            if (is_ball) {
                const int iB = sIJ[1];
                // P2: integrate everything (threads 128..383) || h1 (threads 0..127)
                if (tid >= 128 && tid < 384) {
                    int b = tid - 128;
                    float4 v = own[b];
                    v.x = fmaf(v.z, dte, v.x); v.y = fmaf(v.w, dte, v.y);
                    own[b] = v;
                    float4 c = bb0[b];
                    c.x = fmaf(c.z, dte, c.x); c.y = fmaf(c.w, dte, c.y);
                    bb0[b] = c;
                    posA[b] = make_float2(c.x, c.y);
                }
                if (tid < 2*HID) {
                    int sel = tid >> 6, o = tid & (HID-1);
                    float4 si = snap[sel*2], sj = snap[sel*2 + 1];
                    float dx = sj.x - si.x, dy = sj.y - si.y;
                    float dist = fmaxf(sqrtf(dx*dx + dy*dy), 1e-8f);
                    float nx = dx / dist, ny = dy / dist;
                    float ap = (sj.z - si.z)*nx + (sj.w - si.w)*ny;
                    float pre = dist*w1s[2*o] + ap*w1s[2*o+1] + b1s[o];
                    h1buf[sel*HID + o] = silu_f(pre);
                }
                if (tid == NTH-1)
                    sMotion += 2.0f * sqrtf(__int_as_float(sVmax2i)) * dte;
                __syncthreads();                          // ---- BAR C ----
                if (tid < 2*HID) {
                    int sel = tid >> 6, o = tid & (HID-1);
                    float acc = b2s[o];
                    const float* hb = &h1buf[sel*HID];
                    #pragma unroll
                    for (int k2 = 0; k2 < HID; ++k2) acc += w2t[k2*HID + o]*hb[k2];
                    h2buf[sel*HID + o] = w3s[o] * silu_f(acc);
                }
                __syncthreads();                          // ---- BAR D ----
                if (warp == 0 || warp == 2) {
                    int sel = warp >> 1;
                    float v = h2buf[sel*HID + lane] + h2buf[sel*HID + 32 + lane];
                    #pragma unroll
                    for (int off = 16; off > 0; off >>= 1)
                        v += __shfl_down_sync(0xFFFFFFFFu, v, off);
                    if (lane == 0) {
                        float impv = v + b3v;
                        float4 si = snap[sel*2], sj = snap[sel*2 + 1];
                        float dx = sj.x - si.x, dy = sj.y - si.y;
                        float dist = fmaxf(sqrtf(dx*dx + dy*dy), 1e-8f);
                        float nx = dx/dist, ny = dy/dist;
                        float niz = si.z + impv*nx, niw = si.w + impv*ny;
                        float njz = sj.z - impv*nx, njw = sj.w - impv*ny;
                        float4* S = sel ? bb0 : own;
                        S[iA].z = niz;  S[iA].w = niw;
                        S[iB].z = njz;  S[iB].w = njw;
                        if (sel == 1) {
                            float sp = fmaxf(niz*niz + niw*niw, njz*njz + njw*njw);
                            atomicMax(&sVmax2i, __float_as_int(sp));
                        }
                    }
                }
                __syncthreads();                          // ---- BAR E ----
            } else {
                const int wsel = sIJ[1];
                // P2w: integrate all except iA; wall-apply from snapshots on threads 0/1
                if (tid >= 128 && tid < 384) {
                    int b = tid - 128;
                    if (b != iA) {
                        float4 v = own[b];
                        v.x = fmaf(v.z, dte, v.x); v.y = fmaf(v.w, dte, v.y);
                        own[b] = v;
                        float4 c = bb0[b];
                        c.x = fmaf(c.z, dte, c.x); c.y = fmaf(c.w, dte, c.y);
                        bb0[b] = c;
                        posA[b] = make_float2(c.x, c.y);
                    }
                }
                if (tid < 2) {
                    float4 si = tid ? snap[2] : snap[0];   // integrated state of iA
                    float wnx = 0.0f, wny = 0.0f, wp = 0.0f;
                    if      (wsel == 0) { wnx =  1.0f; }
                    else if (wsel == 1) { wnx = -1.0f; wp = -10.0f; }
                    else if (wsel == 2) { wny =  1.0f; }
                    else                { wny = -1.0f; wp = -10.0f; }
                    float vn  = si.z*wnx + si.w*wny;
                    float nvx = si.z - 2.0f*vn*wnx;
                    float nvy = si.w - 2.0f*vn*wny;
                    float pn  = si.x*wnx + si.y*wny;
                    float pen = fmaxf(wp + rr - pn, 0.0f);
                    float npx = si.x + pen*wnx, npy = si.y + pen*wny;
                    float4* S = tid ? bb0 : own;
                    S[iA] = make_float4(npx, npy, nvx, nvy);
                    if (tid == 1) {
                        posA[iA] = make_float2(npx, npy);
                        sMotion += 2.0f * sqrtf(__int_as_float(sVmax2i)) * dte + pen;
                    }
                }
                __syncthreads();                          // ---- BAR C(w) ----
            }
        }  // events

        // ---- step end: integrate remaining time, emit, reset key slots ----
        __syncthreads();
        const float dte2 = (t_e > t_c + 1e-10f) ? (t_e - t_c) : 0.0f;
        if (tid < NB) {
            float4 v = own[tid];
            v.x = fmaf(v.z, dte2, v.x); v.y = fmaf(v.w, dte2, v.y);
            own[tid] = v;
            float4 c = bb0[tid];
            c.x = fmaf(c.z, dte2, c.x); c.y = fmaf(c.w, dte2, c.y);
            bb0[tid] = c;
            posA[tid] = make_float2(c.x, c.y);
            reinterpret_cast<float4*>(g_out)[((long)(s+1)*BATCHN + bidx)*NB + tid] = v;
        }
        if (tid < MAXEV) { sKBev[tid] = ~0ull; sKWev[tid] = ~0ull; }
        if (tid == 0)
            sMotion += 2.0f * sqrtf(__int_as_float(sVmax2i)) * dte2;
        __syncthreads();
    }
}

extern "C" void kernel_launch(void* const* d_in, const int* in_sizes, int n_in,
                              void* d_out, int out_size) {
    (void)in_sizes; (void)n_in; (void)out_size;
    hybrid_rollout<<<BATCHN, NTH>>>(
        (const float*)d_in[0], (const float*)d_in[1],
        (const float*)d_in[2], (const float*)d_in[3],
        (const float*)d_in[4], (const float*)d_in[5],
        (const float*)d_in[6], (const float*)d_in[7],
        (float*)d_out);
}

// round 6
// speedup vs baseline: 1.6115x; 1.1002x over previous
#include <cuda_runtime.h>
#include <cuda_bf16.h>
#include <math.h>

#define NB 256
#define BATCHN 128
#define NSTEPS 100
#define MAXEV 5
#define HID 64
#define NTH 512
#define NWARP (NTH/32)
#define SEGCAP 385
#define MARGIN 1.0f

__device__ __forceinline__ float silu_f(float x) {
    return x / (1.0f + expf(-x));
}

__global__ __launch_bounds__(NTH, 1)
void hybrid_rollout(const float* __restrict__ g_state,
                    const float* __restrict__ g_radii,
                    const float* __restrict__ g_W1,
                    const float* __restrict__ g_b1,
                    const float* __restrict__ g_W2,
                    const float* __restrict__ g_b2,
                    const float* __restrict__ g_W3,
                    const float* __restrict__ g_b3,
                    float* __restrict__ g_out)
{
    __shared__ float4 own[NB];                 // this block's batch element
    __shared__ float4 bb0[NB];                 // private copy of batch element 0
    __shared__ float2 posA[NB];                // position mirror of bb0 (broad phase)
    __shared__ float w2t[HID*HID];
    __shared__ float w1s[2*HID];
    __shared__ float b1s[HID], b2s[HID], w3s[HID];
    __shared__ float h1buf[2*HID], h2buf[2*HID];
    __shared__ unsigned long long redB[NWARP], redW[NWARP];
    __shared__ float vmaxW[NWARP];
    __shared__ int nCandW[NWARP];
    __shared__ int candList[NWARP*SEGCAP];     // per-warp segments, packed (lo<<8)|hi
    __shared__ int sVmax2i;                    // float bits of max speed^2 over bb0
    __shared__ float sMotion;
    __shared__ int sOverflow;
    __shared__ float sb3, srr;

    const int tid  = threadIdx.x;
    const int bidx = blockIdx.x;
    const int i0   = tid & (NB-1);
    const int half = tid >> 8;
    const int lane = tid & 31;
    const int warp = tid >> 5;

    // ---- setup ----
    if (tid < NB) {
        float4 v = reinterpret_cast<const float4*>(g_state)[bidx*NB + tid];
        own[tid] = v;
        float4 c = reinterpret_cast<const float4*>(g_state)[tid];
        bb0[tid] = c;
        posA[tid] = make_float2(c.x, c.y);
        reinterpret_cast<float4*>(g_out)[bidx*NB + tid] = v;
    }
    for (int k = tid; k < HID*HID; k += NTH) {
        int o = k >> 6, c = k & 63;
        w2t[c*HID + o] = g_W2[k];
    }
    if (tid < 2*HID) w1s[tid] = g_W1[tid];
    if (tid < HID) { b1s[tid] = g_b1[tid]; b2s[tid] = g_b2[tid]; w3s[tid] = g_W3[tid]; }
    if (tid == 0) {
        sb3 = g_b3[0]; srr = g_radii[0];
        sMotion = 1e30f; sVmax2i = 0; sOverflow = 0;
    }
    __syncthreads();

    const float rr    = srr;
    const float two_r = rr + rr;
    const float cut   = two_r + 0.051f;        // exact narrow cutoff (gap>0.05 -> done)
    const float c2    = cut * cut;
    const float cute  = cut + MARGIN;          // broad-phase cutoff
    const float c2e   = cute * cute;
    const float b3v   = sb3;

    for (int s = 0; s < NSTEPS; ++s) {
        const float t_s = (float)s * 0.05f;
        const float t_e = t_s + 0.05f;
        float t_c = t_s;

        for (int ev = 0; ev < MAXEV; ++ev) {
            // ================= P0: detection =================
            const bool rebuild = (sOverflow != 0) || (sMotion >= MARGIN);
            const float4 me = bb0[i0];
            unsigned long long bk = ~0ull, wk = ~0ull;

            if (rebuild) {
                // warp-max of speed^2 (no atomics)
                float m = me.z*me.z + me.w*me.w;
                #pragma unroll
                for (int off = 16; off > 0; off >>= 1)
                    m = fmaxf(m, __shfl_down_sync(0xFFFFFFFFu, m, off));
                if (lane == 0) vmaxW[warp] = m;

                int cnt = 0;
                const int segBase = warp * SEGCAP;
                for (int d = 1 + half; d <= 128; d += 2) {
                    if (d == 128 && i0 >= 128) break;      // warp-uniform
                    int j = (i0 + d) & (NB-1);
                    float2 pj = posA[j];
                    float dx = pj.x - me.x, dy = pj.y - me.y;
                    float d2 = dx*dx + dy*dy;
                    bool push = (d2 <= c2e);
                    unsigned msk = __ballot_sync(0xFFFFFFFFu, push);
                    if (push) {
                        int lo = (i0 < j) ? i0 : j;
                        int hi = (i0 < j) ? j : i0;
                        int slot = cnt + __popc(msk & ((1u << lane) - 1u));
                        if (slot < SEGCAP) candList[segBase + slot] = (lo << 8) | hi;
                        float4 oj = bb0[j];
                        float dvx = oj.z - me.z, dvy = oj.w - me.w;
                        if (dvx*dx + dvy*dy < 0.0f && d2 <= c2) {
                            unsigned long long key =
                                ((unsigned long long)__float_as_uint(d2) << 32) |
                                (unsigned)((lo << 8) | hi);
                            if (key < bk) bk = key;
                        }
                    }
                    cnt += __popc(msk);
                }
                if (lane == 0) nCandW[warp] = cnt;
            } else {
                const int seg  = tid & (NWARP-1);
                const int e0   = tid >> 4;                 // 0..31
                int n = nCandW[seg]; if (n > SEGCAP) n = SEGCAP;
                const int base = seg * SEGCAP;
                for (int e = e0; e < n; e += 32) {
                    int p = candList[base + e];
                    int lo = p >> 8, hi = p & 255;
                    float4 si = bb0[lo], sj = bb0[hi];
                    float dx = sj.x - si.x, dy = sj.y - si.y;
                    float d2 = dx*dx + dy*dy;
                    float dvx = sj.z - si.z, dvy = sj.w - si.w;
                    if (dvx*dx + dvy*dy < 0.0f && d2 <= c2) {
                        unsigned long long key =
                            ((unsigned long long)__float_as_uint(d2) << 32) | (unsigned)p;
                        if (key < bk) bk = key;
                    }
                }
            }

            // wall candidates
            if (half == 0) {
                float gs[4]; bool vs[4];
                gs[0] = me.x - rr;          vs[0] = me.z < 0.0f;
                gs[1] = 10.0f - me.x - rr;  vs[1] = me.z > 0.0f;
                gs[2] = me.y - rr;          vs[2] = me.w < 0.0f;
                gs[3] = 10.0f - me.y - rr;  vs[3] = me.w > 0.0f;
                #pragma unroll
                for (int w = 0; w < 4; ++w) {
                    if (vs[w]) {
                        unsigned u = __float_as_uint(gs[w]);
                        u = (u & 0x80000000u) ? ~u : (u | 0x80000000u);
                        unsigned long long key = ((unsigned long long)u << 32) | (unsigned)(i0*4 + w);
                        if (key < wk) wk = key;
                    }
                }
            }

            // warp tree -> lane0 STS -> BAR -> redundant 16-way butterfly fold
            #pragma unroll
            for (int off = 16; off > 0; off >>= 1) {
                unsigned long long ob = __shfl_down_sync(0xFFFFFFFFu, bk, off);
                unsigned long long ow = __shfl_down_sync(0xFFFFFFFFu, wk, off);
                if (ob < bk) bk = ob;
                if (ow < wk) wk = ow;
            }
            if (lane == 0) { redB[warp] = bk; redW[warp] = wk; }
            __syncthreads();                              // ---- BAR A ----

            // rebuild bookkeeping on one non-integrator thread (no races: others only read)
            if (rebuild && tid == NTH-1) {
                float vm = vmaxW[0];
                #pragma unroll
                for (int w = 1; w < NWARP; ++w) vm = fmaxf(vm, vmaxW[w]);
                sVmax2i = __float_as_int(vm);
                int ov = 0;
                #pragma unroll
                for (int w = 0; w < NWARP; ++w) ov |= (nCandW[w] > SEGCAP);
                if (ov) sOverflow = 1;
                sMotion = 0.0f;
            }

            bk = redB[lane & (NWARP-1)];
            wk = redW[lane & (NWARP-1)];
            #pragma unroll
            for (int off = 8; off > 0; off >>= 1) {
                unsigned long long ob = __shfl_xor_sync(0xFFFFFFFFu, bk, off);
                unsigned long long ow = __shfl_xor_sync(0xFFFFFFFFu, wk, off);
                if (ob < bk) bk = ob;
                if (ow < wk) wk = ow;
            }

            float gapB = 1e30f, gapW = 1e30f;
            if (bk != ~0ull) gapB = sqrtf(__uint_as_float((unsigned)(bk >> 32))) - two_r;
            if (wk != ~0ull) {
                unsigned u = (unsigned)(wk >> 32);
                u = (u & 0x80000000u) ? (u ^ 0x80000000u) : ~u;
                gapW = __uint_as_float(u);
            }
            const bool  is_ball = (gapB <= gapW);
            const float gap     = is_ball ? gapB : gapW;
            if (gap > 0.05f) break;                        // no_event -> done (step-end bar orders)

            // redundant decode + flags on ALL threads (reads of bb0[iA/iB] are race-free:
            // integrators skip iA/iB; iA writes happen only after a later barrier)
            int iA, iB = 0, wsel = 0;
            float app;
            if (is_ball) {
                iA = (int)(((unsigned)bk >> 8) & 255u);
                iB = (int)((unsigned)bk & 255u);
                float4 pi = bb0[iA], pj = bb0[iB];
                float nx = pj.x - pi.x, ny = pj.y - pi.y;
                float L = sqrtf(nx*nx + ny*ny);
                app = -(((pj.z - pi.z)*nx)/L + ((pj.w - pi.w)*ny)/L);
            } else {
                iA = (int)((unsigned)wk >> 2);
                wsel = (int)((unsigned)wk & 3u);
                float4 pi = bb0[iA];
                app = fabsf(fmaxf(pi.z, pi.w));
            }
            const float t_ev  = t_c + gap / fmaxf(app, 1e-6f);
            const bool case_a = (gap <= 0.0f);
            const bool case_b = (!case_a) && (app > 1e-6f) && (t_ev < t_e);
            if (!case_a && !case_b) break;                 // done
            const float dte = case_b ? ((t_ev > t_c + 1e-10f) ? (t_ev - t_c) : 0.0f) : 0.0f;
            if (case_b) t_c = t_ev;

            if (is_ball) {
                // P2: h1 (tid<128) || integrate all b except iA,iB (tid 128..383) || sMotion (511)
                if (tid < 2*HID) {
                    int sel = tid >> 6, o = tid & (HID-1);
                    const float4* S = sel ? bb0 : own;
                    float4 si = S[iA], sj = S[iB];
                    float six = fmaf(si.z, dte, si.x), siy = fmaf(si.w, dte, si.y);
                    float sjx = fmaf(sj.z, dte, sj.x), sjy = fmaf(sj.w, dte, sj.y);
                    float dx = sjx - six, dy = sjy - siy;
                    float dist = fmaxf(sqrtf(dx*dx + dy*dy), 1e-8f);
                    float nx = dx / dist, ny = dy / dist;
                    float ap = (sj.z - si.z)*nx + (sj.w - si.w)*ny;
                    float pre = dist*w1s[2*o] + ap*w1s[2*o+1] + b1s[o];
                    h1buf[sel*HID + o] = silu_f(pre);
                } else if (tid < 384) {
                    int b = tid - 128;
                    if (b != iA && b != iB) {
                        float4 v = own[b];
                        v.x = fmaf(v.z, dte, v.x); v.y = fmaf(v.w, dte, v.y);
                        own[b] = v;
                        float4 c = bb0[b];
                        c.x = fmaf(c.z, dte, c.x); c.y = fmaf(c.w, dte, c.y);
                        bb0[b] = c;
                        posA[b] = make_float2(c.x, c.y);
                    }
                } else if (tid == NTH-1) {
                    sMotion += 2.0f * sqrtf(__int_as_float(sVmax2i)) * dte;
                }
                __syncthreads();                          // ---- BAR C ----
                if (tid < 2*HID) {
                    int sel = tid >> 6, o = tid & (HID-1);
                    float acc = b2s[o];
                    const float* hb = &h1buf[sel*HID];
                    #pragma unroll
                    for (int k2 = 0; k2 < HID; ++k2) acc += w2t[k2*HID + o]*hb[k2];
                    h2buf[sel*HID + o] = w3s[o] * silu_f(acc);
                }
                __syncthreads();                          // ---- BAR D ----
                if (warp == 0 || warp == 2) {
                    int sel = warp >> 1;
                    float v = h2buf[sel*HID + lane] + h2buf[sel*HID + 32 + lane];
                    #pragma unroll
                    for (int off = 16; off > 0; off >>= 1)
                        v += __shfl_down_sync(0xFFFFFFFFu, v, off);
                    if (lane == 0) {
                        float impv = v + b3v;
                        float4* S = sel ? bb0 : own;
                        float4 si = S[iA], sj = S[iB];      // still pre-event values
                        float six = fmaf(si.z, dte, si.x), siy = fmaf(si.w, dte, si.y);
                        float sjx = fmaf(sj.z, dte, sj.x), sjy = fmaf(sj.w, dte, sj.y);
                        float dx = sjx - six, dy = sjy - siy;
                        float dist = fmaxf(sqrtf(dx*dx + dy*dy), 1e-8f);
                        float nx = dx/dist, ny = dy/dist;
                        float niz = si.z + impv*nx, niw = si.w + impv*ny;
                        float njz = sj.z - impv*nx, njw = sj.w - impv*ny;
                        S[iA] = make_float4(six, siy, niz, niw);
                        S[iB] = make_float4(sjx, sjy, njz, njw);
                        if (sel == 1) {
                            posA[iA] = make_float2(six, siy);
                            posA[iB] = make_float2(sjx, sjy);
                            float sp = fmaxf(niz*niz + niw*niw, njz*njz + njw*njw);
                            atomicMax(&sVmax2i, __float_as_int(sp));
                        }
                    }
                }
                __syncthreads();                          // ---- BAR E ----
            } else {
                // wall: compute results + integrate (b != iA) pre-barrier; write iA post-barrier
                float4 res; float pen = 0.0f;
                if (tid < 2) {
                    const float4 si = tid ? bb0[iA] : own[iA];
                    float six = fmaf(si.z, dte, si.x), siy = fmaf(si.w, dte, si.y);
                    float wnx = 0.0f, wny = 0.0f, wp = 0.0f;
                    if      (wsel == 0) { wnx =  1.0f; }
                    else if (wsel == 1) { wnx = -1.0f; wp = -10.0f; }
                    else if (wsel == 2) { wny =  1.0f; }
                    else                { wny = -1.0f; wp = -10.0f; }
                    float vn  = si.z*wnx + si.w*wny;
                    float nvx = si.z - 2.0f*vn*wnx;
                    float nvy = si.w - 2.0f*vn*wny;
                    float pn  = six*wnx + siy*wny;
                    pen = fmaxf(wp + rr - pn, 0.0f);
                    res = make_float4(six + pen*wnx, siy + pen*wny, nvx, nvy);
                } else if (tid >= 128 && tid < 384) {
                    int b = tid - 128;
                    if (b != iA) {
                        float4 v = own[b];
                        v.x = fmaf(v.z, dte, v.x); v.y = fmaf(v.w, dte, v.y);
                        own[b] = v;
                        float4 c = bb0[b];
                        c.x = fmaf(c.z, dte, c.x); c.y = fmaf(c.w, dte, c.y);
                        bb0[b] = c;
                        posA[b] = make_float2(c.x, c.y);
                    }
                }
                __syncthreads();                          // ---- BAR W1 (decode reads done)
                if (tid < 2) {
                    float4* S = tid ? bb0 : own;
                    S[iA] = res;
                    if (tid == 1) {
                        posA[iA] = make_float2(res.x, res.y);
                        sMotion += 2.0f * sqrtf(__int_as_float(sVmax2i)) * dte + pen;
                    }
                }
                __syncthreads();                          // ---- BAR W2 ----
            }
        }  // events

        // ---- step end ----
        __syncthreads();                                  // orders break-path reads vs writes
        const float dte2 = (t_e > t_c + 1e-10f) ? (t_e - t_c) : 0.0f;
        if (tid < NB) {
            float4 v = own[tid];
            v.x = fmaf(v.z, dte2, v.x); v.y = fmaf(v.w, dte2, v.y);
            own[tid] = v;
            float4 c = bb0[tid];
            c.x = fmaf(c.z, dte2, c.x); c.y = fmaf(c.w, dte2, c.y);
            bb0[tid] = c;
            posA[tid] = make_float2(c.x, c.y);
            reinterpret_cast<float4*>(g_out)[((long)(s+1)*BATCHN + bidx)*NB + tid] = v;
        }
        if (tid == 0)
            sMotion += 2.0f * sqrtf(__int_as_float(sVmax2i)) * dte2;
        __syncthreads();
    }
}

extern "C" void kernel_launch(void* const* d_in, const int* in_sizes, int n_in,
                              void* d_out, int out_size) {
    (void)in_sizes; (void)n_in; (void)out_size;
    hybrid_rollout<<<BATCHN, NTH>>>(
        (const float*)d_in[0], (const float*)d_in[1],
        (const float*)d_in[2], (const float*)d_in[3],
        (const float*)d_in[4], (const float*)d_in[5],
        (const float*)d_in[6], (const float*)d_in[7],
        (float*)d_out);
}